// round 14
// baseline (speedup 1.0000x reference)
#include <cuda_runtime.h>
#include <cuda_fp16.h>

#define NN 50000
#define NE 800000
#define CH 64
#define ETOT (NE + NN)
#define NBLK ((NN + 255) / 256)   // 196 scan blocks

// ---------------- scratch (device globals; no allocation allowed) ----------
// packed per-node quad rows: 16 quads per node, 16B each
__device__ uint4 g_ab[NN * 16];   // {l[4q..4q+3] half, r[4q..4q+3] half}  (aggA)
__device__ uint4 g_bc[NN * 16];   // {r[4q..4q+3] half, ftr[4q..4q+3] half} (aggB)
__device__ float g_res[NN * CH];
// CSR build
__device__ int g_cnt[NN + 1];      // histogram
__device__ int g_off[NN + 1];      // CSR offsets
__device__ int g_epos[ETOT];       // per-edge rank within its dst segment
__device__ int g_bsum[NBLK];       // per-block sums
__device__ int g_bscan[NBLK];      // scanned block sums
__device__ int g_ssrc[ETOT];       // src node id per dst-sorted edge

__device__ __forceinline__ float fast_rcp(float x) {
    float r;
    asm("rcp.approx.f32 %0, %1;" : "=f"(r) : "f"(x));
    return r;
}

__device__ __forceinline__ float expsig(float x) {
    // exp(sigmoid(x)); sigmoid in (0,1) so exp in (1,e): overflow-safe,
    // and exp(v)/sum == exp(v-mx)/sum(exp(v-mx)) exactly in math.
    float u = __expf(-x);
    float s = fast_rcp(1.f + u);
    return __expf(s);
}

// convert two packed half2 words to float4
__device__ __forceinline__ float4 h4f(unsigned lo, unsigned hi) {
    __half2 h0 = *reinterpret_cast<__half2*>(&lo);
    __half2 h1 = *reinterpret_cast<__half2*>(&hi);
    float2 f0 = __half22float2(h0);
    float2 f1 = __half22float2(h1);
    return make_float4(f0.x, f0.y, f1.x, f1.y);
}

// pack float4 into two half2 words
__device__ __forceinline__ void f4h(float4 v, unsigned& lo, unsigned& hi) {
    __half2 h0 = __floats2half2_rn(v.x, v.y);
    __half2 h1 = __floats2half2_rn(v.z, v.w);
    lo = *reinterpret_cast<unsigned*>(&h0);
    hi = *reinterpret_cast<unsigned*>(&h1);
}

// ================= node pass: minmax + 3 GEMVs, 2 nodes per thread =========
__global__ void __launch_bounds__(256) node_proj_kernel(
        const float* __restrict__ ndata,
        const float* __restrict__ W1,   const float* __restrict__ b1,
        const float* __restrict__ W2,   const float* __restrict__ b2,
        const float* __restrict__ Wres, const float* __restrict__ bres) {
    __shared__ float sx[32][CH];

    int t  = threadIdx.x;
    int g  = t >> 4;          // group 0..15
    int q  = t & 15;          // feature quad
    int n0 = blockIdx.x * 32 + g;
    int n1 = n0 + 16;
    bool v0 = (n0 < NN), v1 = (n1 < NN);

    float4 x0 = v0 ? reinterpret_cast<const float4*>(ndata + n0 * CH)[q]
                   : make_float4(0.f, 0.f, 0.f, 0.f);
    float4 x1 = v1 ? reinterpret_cast<const float4*>(ndata + n1 * CH)[q]
                   : make_float4(0.f, 0.f, 0.f, 0.f);

    float mn0 = fminf(fminf(x0.x, x0.y), fminf(x0.z, x0.w));
    float mx0 = fmaxf(fmaxf(x0.x, x0.y), fmaxf(x0.z, x0.w));
    float mn1 = fminf(fminf(x1.x, x1.y), fminf(x1.z, x1.w));
    float mx1 = fmaxf(fmaxf(x1.x, x1.y), fmaxf(x1.z, x1.w));
    #pragma unroll
    for (int off = 8; off > 0; off >>= 1) {
        mn0 = fminf(mn0, __shfl_xor_sync(0xffffffffu, mn0, off));
        mx0 = fmaxf(mx0, __shfl_xor_sync(0xffffffffu, mx0, off));
        mn1 = fminf(mn1, __shfl_xor_sync(0xffffffffu, mn1, off));
        mx1 = fmaxf(mx1, __shfl_xor_sync(0xffffffffu, mx1, off));
    }
    float inv0 = __frcp_rn(mx0 - mn0 + 1e-5f);
    float inv1 = __frcp_rn(mx1 - mn1 + 1e-5f);
    sx[g][q*4+0] = (x0.x-mn0)*inv0; sx[g][q*4+1] = (x0.y-mn0)*inv0;
    sx[g][q*4+2] = (x0.z-mn0)*inv0; sx[g][q*4+3] = (x0.w-mn0)*inv0;
    sx[g+16][q*4+0] = (x1.x-mn1)*inv1; sx[g+16][q*4+1] = (x1.y-mn1)*inv1;
    sx[g+16][q*4+2] = (x1.z-mn1)*inv1; sx[g+16][q*4+3] = (x1.w-mn1)*inv1;
    __syncthreads();

    if (!v0) return;

    float4 bb1 = __ldg(reinterpret_cast<const float4*>(b1)   + q);
    float4 bb2 = __ldg(reinterpret_cast<const float4*>(b2)   + q);
    float4 bbr = __ldg(reinterpret_cast<const float4*>(bres) + q);
    float4 a1_0 = bb1, a2_0 = bb2, ar_0 = bbr;
    float4 a1_1 = bb1, a2_1 = bb2, ar_1 = bbr;

    #pragma unroll
    for (int k = 0; k < CH; k++) {
        float4 w1 = __ldg(reinterpret_cast<const float4*>(W1   + k * CH) + q);
        float4 w2 = __ldg(reinterpret_cast<const float4*>(W2   + k * CH) + q);
        float4 wr = __ldg(reinterpret_cast<const float4*>(Wres + k * CH) + q);
        float xa = sx[g][k];
        float xb = sx[g+16][k];
        a1_0.x = fmaf(xa,w1.x,a1_0.x); a1_0.y = fmaf(xa,w1.y,a1_0.y);
        a1_0.z = fmaf(xa,w1.z,a1_0.z); a1_0.w = fmaf(xa,w1.w,a1_0.w);
        a2_0.x = fmaf(xa,w2.x,a2_0.x); a2_0.y = fmaf(xa,w2.y,a2_0.y);
        a2_0.z = fmaf(xa,w2.z,a2_0.z); a2_0.w = fmaf(xa,w2.w,a2_0.w);
        ar_0.x = fmaf(xa,wr.x,ar_0.x); ar_0.y = fmaf(xa,wr.y,ar_0.y);
        ar_0.z = fmaf(xa,wr.z,ar_0.z); ar_0.w = fmaf(xa,wr.w,ar_0.w);
        a1_1.x = fmaf(xb,w1.x,a1_1.x); a1_1.y = fmaf(xb,w1.y,a1_1.y);
        a1_1.z = fmaf(xb,w1.z,a1_1.z); a1_1.w = fmaf(xb,w1.w,a1_1.w);
        a2_1.x = fmaf(xb,w2.x,a2_1.x); a2_1.y = fmaf(xb,w2.y,a2_1.y);
        a2_1.z = fmaf(xb,w2.z,a2_1.z); a2_1.w = fmaf(xb,w2.w,a2_1.w);
        ar_1.x = fmaf(xb,wr.x,ar_1.x); ar_1.y = fmaf(xb,wr.y,ar_1.y);
        ar_1.z = fmaf(xb,wr.z,ar_1.z); ar_1.w = fmaf(xb,wr.w,ar_1.w);
    }

    {
        uint4 ab;
        f4h(a1_0, ab.x, ab.y);
        f4h(a2_0, ab.z, ab.w);
        g_ab[n0 * 16 + q] = ab;
        reinterpret_cast<float2*>(&g_bc[n0 * 16 + q])[0] =
            *reinterpret_cast<float2*>(&ab.z);   // r halves
        reinterpret_cast<float4*>(g_res + n0 * CH)[q] = ar_0;
    }
    if (v1) {
        uint4 ab;
        f4h(a1_1, ab.x, ab.y);
        f4h(a2_1, ab.z, ab.w);
        g_ab[n1 * 16 + q] = ab;
        reinterpret_cast<float2*>(&g_bc[n1 * 16 + q])[0] =
            *reinterpret_cast<float2*>(&ab.z);
        reinterpret_cast<float4*>(g_res + n1 * CH)[q] = ar_1;
    }
}

// ================= CSR build (NBLK cascade — do not restructure) ============
__global__ void init_cnt_kernel() {
    int i = blockIdx.x * blockDim.x + threadIdx.x;
    if (i <= NN) g_cnt[i] = 0;
}

// 4 edges per thread: 4 independent atomic chains in flight (MLP=4)
__global__ void hist_kernel(const int* __restrict__ dst) {
    int e = (blockIdx.x * blockDim.x + threadIdx.x) * 4;
    if (e >= ETOT) return;
    if (e + 3 < NE) {
        int4 d4 = __ldg(reinterpret_cast<const int4*>(dst + e));
        g_epos[e]     = atomicAdd(&g_cnt[d4.x], 1);
        g_epos[e + 1] = atomicAdd(&g_cnt[d4.y], 1);
        g_epos[e + 2] = atomicAdd(&g_cnt[d4.z], 1);
        g_epos[e + 3] = atomicAdd(&g_cnt[d4.w], 1);
    } else {
        #pragma unroll
        for (int j = 0; j < 4; j++) {
            int ej = e + j;
            if (ej >= ETOT) break;
            int d = (ej < NE) ? __ldg(&dst[ej]) : (ej - NE);
            g_epos[ej] = atomicAdd(&g_cnt[d], 1);
        }
    }
}

__global__ void scan1_kernel() {
    __shared__ int sm[256];
    int t = threadIdx.x;
    int i = blockIdx.x * 256 + t;
    sm[t] = (i < NN) ? g_cnt[i] : 0;
    __syncthreads();
    #pragma unroll
    for (int o = 128; o > 0; o >>= 1) {
        if (t < o) sm[t] += sm[t + o];
        __syncthreads();
    }
    if (t == 0) g_bsum[blockIdx.x] = sm[0];
}

__global__ void scan2_kernel() {
    __shared__ int sm[256];
    int t = threadIdx.x;
    int v = (t < NBLK) ? g_bsum[t] : 0;
    sm[t] = v;
    __syncthreads();
    #pragma unroll
    for (int o = 1; o < 256; o <<= 1) {
        int add = (t >= o) ? sm[t - o] : 0;
        __syncthreads();
        sm[t] += add;
        __syncthreads();
    }
    if (t < NBLK) g_bscan[t] = sm[t] - v;   // exclusive
}

__global__ void scan3_kernel() {
    __shared__ int sm[256];
    int t = threadIdx.x;
    int i = blockIdx.x * 256 + t;
    int v = (i < NN) ? g_cnt[i] : 0;
    sm[t] = v;
    __syncthreads();
    #pragma unroll
    for (int o = 1; o < 256; o <<= 1) {
        int add = (t >= o) ? sm[t - o] : 0;
        __syncthreads();
        sm[t] += add;
        __syncthreads();
    }
    if (i < NN) {
        g_off[i] = g_bscan[blockIdx.x] + sm[t] - v;
    }
    if (i == 0) g_off[NN] = ETOT;
}

// atomic-free scatter, 4 edges per thread (4 independent chains)
__global__ void scatter_kernel(const int* __restrict__ src,
                               const int* __restrict__ dst) {
    int e = (blockIdx.x * blockDim.x + threadIdx.x) * 4;
    if (e >= ETOT) return;
    if (e + 3 < NE) {
        int4 d4 = __ldg(reinterpret_cast<const int4*>(dst + e));
        int4 s4 = __ldg(reinterpret_cast<const int4*>(src + e));
        int4 p4 = *reinterpret_cast<const int4*>(g_epos + e);
        int o0 = __ldg(&g_off[d4.x]);
        int o1 = __ldg(&g_off[d4.y]);
        int o2 = __ldg(&g_off[d4.z]);
        int o3 = __ldg(&g_off[d4.w]);
        g_ssrc[o0 + p4.x] = s4.x;
        g_ssrc[o1 + p4.y] = s4.y;
        g_ssrc[o2 + p4.z] = s4.z;
        g_ssrc[o3 + p4.w] = s4.w;
    } else {
        #pragma unroll
        for (int j = 0; j < 4; j++) {
            int ej = e + j;
            if (ej >= ETOT) break;
            int s, d;
            if (ej < NE) { s = __ldg(&src[ej]); d = __ldg(&dst[ej]); }
            else         { s = ej - NE; d = s; }
            g_ssrc[__ldg(&g_off[d]) + g_epos[ej]] = s;
        }
    }
}

// ================= agg pass A: ftr[n] = sum(r[s]*el) / sum(el) ===============
// el = expsig(l_s + l_n). ONE LDG.128 per edge-lane ({l,r} packed halves).
__global__ void __launch_bounds__(256) aggA_kernel() {
    int n = blockIdx.x * 16 + (threadIdx.x >> 4);
    if (n >= NN) return;
    int q = threadIdx.x & 15;

    uint4 dab = __ldg(&g_ab[n * 16 + q]);
    float4 ldq = h4f(dab.x, dab.y);
    int i0 = __ldg(&g_off[n]);
    int i1 = __ldg(&g_off[n + 1]);

    float4 esum = make_float4(0.f, 0.f, 0.f, 0.f);
    float4 acc  = make_float4(0.f, 0.f, 0.f, 0.f);

    int i = i0;
    for (; i + 2 <= i1; i += 2) {
        int s0 = __ldg(&g_ssrc[i]);
        int s1 = __ldg(&g_ssrc[i + 1]);
        uint4 v0 = __ldg(&g_ab[s0 * 16 + q]);
        uint4 v1 = __ldg(&g_ab[s1 * 16 + q]);
        float4 ls0 = h4f(v0.x, v0.y);
        float4 rs0 = h4f(v0.z, v0.w);
        float4 ls1 = h4f(v1.x, v1.y);
        float4 rs1 = h4f(v1.z, v1.w);
        float4 e0 = make_float4(expsig(ls0.x+ldq.x), expsig(ls0.y+ldq.y),
                                expsig(ls0.z+ldq.z), expsig(ls0.w+ldq.w));
        float4 e1 = make_float4(expsig(ls1.x+ldq.x), expsig(ls1.y+ldq.y),
                                expsig(ls1.z+ldq.z), expsig(ls1.w+ldq.w));
        esum.x += e0.x + e1.x; esum.y += e0.y + e1.y;
        esum.z += e0.z + e1.z; esum.w += e0.w + e1.w;
        acc.x = fmaf(rs0.x, e0.x, acc.x); acc.x = fmaf(rs1.x, e1.x, acc.x);
        acc.y = fmaf(rs0.y, e0.y, acc.y); acc.y = fmaf(rs1.y, e1.y, acc.y);
        acc.z = fmaf(rs0.z, e0.z, acc.z); acc.z = fmaf(rs1.z, e1.z, acc.z);
        acc.w = fmaf(rs0.w, e0.w, acc.w); acc.w = fmaf(rs1.w, e1.w, acc.w);
    }
    if (i < i1) {
        int s0 = __ldg(&g_ssrc[i]);
        uint4 v0 = __ldg(&g_ab[s0 * 16 + q]);
        float4 ls0 = h4f(v0.x, v0.y);
        float4 rs0 = h4f(v0.z, v0.w);
        float4 e0 = make_float4(expsig(ls0.x+ldq.x), expsig(ls0.y+ldq.y),
                                expsig(ls0.z+ldq.z), expsig(ls0.w+ldq.w));
        esum.x += e0.x; esum.y += e0.y; esum.z += e0.z; esum.w += e0.w;
        acc.x = fmaf(rs0.x, e0.x, acc.x); acc.y = fmaf(rs0.y, e0.y, acc.y);
        acc.z = fmaf(rs0.z, e0.z, acc.z); acc.w = fmaf(rs0.w, e0.w, acc.w);
    }

    acc.x *= fast_rcp(esum.x); acc.y *= fast_rcp(esum.y);
    acc.z *= fast_rcp(esum.z); acc.w *= fast_rcp(esum.w);

    unsigned lo, hi;
    f4h(acc, lo, hi);
    float2 p;
    *reinterpret_cast<unsigned*>(&p.x) = lo;
    *reinterpret_cast<unsigned*>(&p.y) = hi;
    reinterpret_cast<float2*>(&g_bc[n * 16 + q])[1] = p;   // ftr halves
}

// ================= agg pass B: out = m0*(sum(ftr[s]*er)/sum(er)) + res =======
__global__ void __launch_bounds__(256) aggB_kernel(const float* __restrict__ m,
                                                   float* __restrict__ out) {
    int n = blockIdx.x * 16 + (threadIdx.x >> 4);
    if (n >= NN) return;
    int q = threadIdx.x & 15;

    uint4 dbc = __ldg(&g_bc[n * 16 + q]);
    float4 rdq = h4f(dbc.x, dbc.y);
    int i0 = __ldg(&g_off[n]);
    int i1 = __ldg(&g_off[n + 1]);

    float4 esum = make_float4(0.f, 0.f, 0.f, 0.f);
    float4 acc  = make_float4(0.f, 0.f, 0.f, 0.f);

    int i = i0;
    for (; i + 2 <= i1; i += 2) {
        int s0 = __ldg(&g_ssrc[i]);
        int s1 = __ldg(&g_ssrc[i + 1]);
        uint4 v0 = __ldg(&g_bc[s0 * 16 + q]);
        uint4 v1 = __ldg(&g_bc[s1 * 16 + q]);
        float4 rs0 = h4f(v0.x, v0.y);
        float4 f0  = h4f(v0.z, v0.w);
        float4 rs1 = h4f(v1.x, v1.y);
        float4 f1  = h4f(v1.z, v1.w);
        float4 e0 = make_float4(expsig(rs0.x+rdq.x), expsig(rs0.y+rdq.y),
                                expsig(rs0.z+rdq.z), expsig(rs0.w+rdq.w));
        float4 e1 = make_float4(expsig(rs1.x+rdq.x), expsig(rs1.y+rdq.y),
                                expsig(rs1.z+rdq.z), expsig(rs1.w+rdq.w));
        esum.x += e0.x + e1.x; esum.y += e0.y + e1.y;
        esum.z += e0.z + e1.z; esum.w += e0.w + e1.w;
        acc.x = fmaf(f0.x, e0.x, acc.x); acc.x = fmaf(f1.x, e1.x, acc.x);
        acc.y = fmaf(f0.y, e0.y, acc.y); acc.y = fmaf(f1.y, e1.y, acc.y);
        acc.z = fmaf(f0.z, e0.z, acc.z); acc.z = fmaf(f1.z, e1.z, acc.z);
        acc.w = fmaf(f0.w, e0.w, acc.w); acc.w = fmaf(f1.w, e1.w, acc.w);
    }
    if (i < i1) {
        int s0 = __ldg(&g_ssrc[i]);
        uint4 v0 = __ldg(&g_bc[s0 * 16 + q]);
        float4 rs0 = h4f(v0.x, v0.y);
        float4 f0  = h4f(v0.z, v0.w);
        float4 e0 = make_float4(expsig(rs0.x+rdq.x), expsig(rs0.y+rdq.y),
                                expsig(rs0.z+rdq.z), expsig(rs0.w+rdq.w));
        esum.x += e0.x; esum.y += e0.y; esum.z += e0.z; esum.w += e0.w;
        acc.x = fmaf(f0.x, e0.x, acc.x); acc.y = fmaf(f0.y, e0.y, acc.y);
        acc.z = fmaf(f0.z, e0.z, acc.z); acc.w = fmaf(f0.w, e0.w, acc.w);
    }

    float4 mv = __ldg(reinterpret_cast<const float4*>(m) + q);
    float4 rv = __ldg(reinterpret_cast<const float4*>(g_res + n * CH) + q);
    float4 o;
    o.x = fmaf(mv.x, acc.x * fast_rcp(esum.x), rv.x);
    o.y = fmaf(mv.y, acc.y * fast_rcp(esum.y), rv.y);
    o.z = fmaf(mv.z, acc.z * fast_rcp(esum.z), rv.z);
    o.w = fmaf(mv.w, acc.w * fast_rcp(esum.w), rv.w);
    reinterpret_cast<float4*>(out + n * CH)[q] = o;
}

extern "C" void kernel_launch(void* const* d_in, const int* in_sizes, int n_in,
                              void* d_out, int out_size) {
    const float* ndata = (const float*)d_in[0];
    const int*   src   = (const int*)d_in[1];
    const int*   dst   = (const int*)d_in[2];
    const float* W1    = (const float*)d_in[3];
    const float* b1    = (const float*)d_in[4];
    const float* W2    = (const float*)d_in[5];
    const float* b2    = (const float*)d_in[6];
    const float* Wres  = (const float*)d_in[7];
    const float* bres  = (const float*)d_in[8];
    const float* m     = (const float*)d_in[9];
    float* out = (float*)d_out;

    // side stream + fork/join events: created once on the first call
    // (the correctness call, which is NOT under graph capture).
    static cudaStream_t s2 = [] {
        cudaStream_t s;
        cudaStreamCreateWithFlags(&s, cudaStreamNonBlocking);
        return s;
    }();
    static cudaEvent_t evFork = [] {
        cudaEvent_t e;
        cudaEventCreateWithFlags(&e, cudaEventDisableTiming);
        return e;
    }();
    static cudaEvent_t evJoin = [] {
        cudaEvent_t e;
        cudaEventCreateWithFlags(&e, cudaEventDisableTiming);
        return e;
    }();

    // fork: s2 becomes a parallel branch of the capture DAG
    cudaEventRecord(evFork, 0);
    cudaStreamWaitEvent(s2, evFork, 0);

    // branch A (default stream): node projections
    node_proj_kernel<<<(NN + 31) / 32, 256>>>(ndata, W1, b1, W2, b2, Wres, bres);

    // branch B (s2): CSR build — independent of node_proj
    init_cnt_kernel<<<(NN + 256) / 256, 256, 0, s2>>>();
    hist_kernel<<<(ETOT / 4 + 255) / 256, 256, 0, s2>>>(dst);
    scan1_kernel<<<NBLK, 256, 0, s2>>>();
    scan2_kernel<<<1, 256, 0, s2>>>();
    scan3_kernel<<<NBLK, 256, 0, s2>>>();
    scatter_kernel<<<(ETOT / 4 + 255) / 256, 256, 0, s2>>>(src, dst);

    // join: aggregation needs both branches
    cudaEventRecord(evJoin, s2);
    cudaStreamWaitEvent(0, evJoin, 0);

    aggA_kernel<<<(NN + 15) / 16, 256>>>();
    aggB_kernel<<<(NN + 15) / 16, 256>>>(m, out);
}

// round 15
// speedup vs baseline: 1.0741x; 1.0741x over previous
#include <cuda_runtime.h>
#include <cuda_fp16.h>

#define NN 50000
#define NE 800000
#define CH 64
#define ETOT (NE + NN)
#define NBLK ((NN + 255) / 256)   // 196 scan blocks

// ---------------- scratch (device globals; no allocation allowed) ----------
// packed per-node quad rows: 16 quads per node, 16B each
__device__ uint4 g_ab[NN * 16];   // {l[4q..4q+3] half, r[4q..4q+3] half}  (aggA)
__device__ uint4 g_bc[NN * 16];   // {r[4q..4q+3] half, ftr[4q..4q+3] half} (aggB)
__device__ float g_res[NN * CH];
// CSR build. g_cnt is zero at process start (static zero-init) and is
// re-zeroed by scan3 at the end of every call -> every graph replay starts
// from zeros without a dedicated init kernel.
__device__ int g_cnt[NN + 1];      // histogram (self-cleaning)
__device__ int g_off[NN + 1];      // CSR offsets
__device__ int g_epos[ETOT];       // per-edge rank within its dst segment
__device__ int g_bsum[NBLK];       // per-block sums
__device__ int g_bscan[NBLK];      // scanned block sums
__device__ int g_ssrc[ETOT];       // src node id per dst-sorted edge

__device__ __forceinline__ float fast_rcp(float x) {
    float r;
    asm("rcp.approx.f32 %0, %1;" : "=f"(r) : "f"(x));
    return r;
}

__device__ __forceinline__ float expsig(float x) {
    // exp(sigmoid(x)); sigmoid in (0,1) so exp in (1,e): overflow-safe,
    // and exp(v)/sum == exp(v-mx)/sum(exp(v-mx)) exactly in math.
    float u = __expf(-x);
    float s = fast_rcp(1.f + u);
    return __expf(s);
}

// convert two packed half2 words to float4
__device__ __forceinline__ float4 h4f(unsigned lo, unsigned hi) {
    __half2 h0 = *reinterpret_cast<__half2*>(&lo);
    __half2 h1 = *reinterpret_cast<__half2*>(&hi);
    float2 f0 = __half22float2(h0);
    float2 f1 = __half22float2(h1);
    return make_float4(f0.x, f0.y, f1.x, f1.y);
}

// pack float4 into two half2 words
__device__ __forceinline__ void f4h(float4 v, unsigned& lo, unsigned& hi) {
    __half2 h0 = __floats2half2_rn(v.x, v.y);
    __half2 h1 = __floats2half2_rn(v.z, v.w);
    lo = *reinterpret_cast<unsigned*>(&h0);
    hi = *reinterpret_cast<unsigned*>(&h1);
}

// ================= node pass: minmax + 3 GEMVs, 2 nodes per thread =========
__global__ void __launch_bounds__(256) node_proj_kernel(
        const float* __restrict__ ndata,
        const float* __restrict__ W1,   const float* __restrict__ b1,
        const float* __restrict__ W2,   const float* __restrict__ b2,
        const float* __restrict__ Wres, const float* __restrict__ bres) {
    __shared__ float sx[32][CH];

    int t  = threadIdx.x;
    int g  = t >> 4;          // group 0..15
    int q  = t & 15;          // feature quad
    int n0 = blockIdx.x * 32 + g;
    int n1 = n0 + 16;
    bool v0 = (n0 < NN), v1 = (n1 < NN);

    float4 x0 = v0 ? reinterpret_cast<const float4*>(ndata + n0 * CH)[q]
                   : make_float4(0.f, 0.f, 0.f, 0.f);
    float4 x1 = v1 ? reinterpret_cast<const float4*>(ndata + n1 * CH)[q]
                   : make_float4(0.f, 0.f, 0.f, 0.f);

    float mn0 = fminf(fminf(x0.x, x0.y), fminf(x0.z, x0.w));
    float mx0 = fmaxf(fmaxf(x0.x, x0.y), fmaxf(x0.z, x0.w));
    float mn1 = fminf(fminf(x1.x, x1.y), fminf(x1.z, x1.w));
    float mx1 = fmaxf(fmaxf(x1.x, x1.y), fmaxf(x1.z, x1.w));
    #pragma unroll
    for (int off = 8; off > 0; off >>= 1) {
        mn0 = fminf(mn0, __shfl_xor_sync(0xffffffffu, mn0, off));
        mx0 = fmaxf(mx0, __shfl_xor_sync(0xffffffffu, mx0, off));
        mn1 = fminf(mn1, __shfl_xor_sync(0xffffffffu, mn1, off));
        mx1 = fmaxf(mx1, __shfl_xor_sync(0xffffffffu, mx1, off));
    }
    float inv0 = __frcp_rn(mx0 - mn0 + 1e-5f);
    float inv1 = __frcp_rn(mx1 - mn1 + 1e-5f);
    sx[g][q*4+0] = (x0.x-mn0)*inv0; sx[g][q*4+1] = (x0.y-mn0)*inv0;
    sx[g][q*4+2] = (x0.z-mn0)*inv0; sx[g][q*4+3] = (x0.w-mn0)*inv0;
    sx[g+16][q*4+0] = (x1.x-mn1)*inv1; sx[g+16][q*4+1] = (x1.y-mn1)*inv1;
    sx[g+16][q*4+2] = (x1.z-mn1)*inv1; sx[g+16][q*4+3] = (x1.w-mn1)*inv1;
    __syncthreads();

    if (!v0) return;

    float4 bb1 = __ldg(reinterpret_cast<const float4*>(b1)   + q);
    float4 bb2 = __ldg(reinterpret_cast<const float4*>(b2)   + q);
    float4 bbr = __ldg(reinterpret_cast<const float4*>(bres) + q);
    float4 a1_0 = bb1, a2_0 = bb2, ar_0 = bbr;
    float4 a1_1 = bb1, a2_1 = bb2, ar_1 = bbr;

    #pragma unroll
    for (int k = 0; k < CH; k++) {
        float4 w1 = __ldg(reinterpret_cast<const float4*>(W1   + k * CH) + q);
        float4 w2 = __ldg(reinterpret_cast<const float4*>(W2   + k * CH) + q);
        float4 wr = __ldg(reinterpret_cast<const float4*>(Wres + k * CH) + q);
        float xa = sx[g][k];
        float xb = sx[g+16][k];
        a1_0.x = fmaf(xa,w1.x,a1_0.x); a1_0.y = fmaf(xa,w1.y,a1_0.y);
        a1_0.z = fmaf(xa,w1.z,a1_0.z); a1_0.w = fmaf(xa,w1.w,a1_0.w);
        a2_0.x = fmaf(xa,w2.x,a2_0.x); a2_0.y = fmaf(xa,w2.y,a2_0.y);
        a2_0.z = fmaf(xa,w2.z,a2_0.z); a2_0.w = fmaf(xa,w2.w,a2_0.w);
        ar_0.x = fmaf(xa,wr.x,ar_0.x); ar_0.y = fmaf(xa,wr.y,ar_0.y);
        ar_0.z = fmaf(xa,wr.z,ar_0.z); ar_0.w = fmaf(xa,wr.w,ar_0.w);
        a1_1.x = fmaf(xb,w1.x,a1_1.x); a1_1.y = fmaf(xb,w1.y,a1_1.y);
        a1_1.z = fmaf(xb,w1.z,a1_1.z); a1_1.w = fmaf(xb,w1.w,a1_1.w);
        a2_1.x = fmaf(xb,w2.x,a2_1.x); a2_1.y = fmaf(xb,w2.y,a2_1.y);
        a2_1.z = fmaf(xb,w2.z,a2_1.z); a2_1.w = fmaf(xb,w2.w,a2_1.w);
        ar_1.x = fmaf(xb,wr.x,ar_1.x); ar_1.y = fmaf(xb,wr.y,ar_1.y);
        ar_1.z = fmaf(xb,wr.z,ar_1.z); ar_1.w = fmaf(xb,wr.w,ar_1.w);
    }

    {
        uint4 ab;
        f4h(a1_0, ab.x, ab.y);
        f4h(a2_0, ab.z, ab.w);
        g_ab[n0 * 16 + q] = ab;
        reinterpret_cast<float2*>(&g_bc[n0 * 16 + q])[0] =
            *reinterpret_cast<float2*>(&ab.z);   // r halves
        reinterpret_cast<float4*>(g_res + n0 * CH)[q] = ar_0;
    }
    if (v1) {
        uint4 ab;
        f4h(a1_1, ab.x, ab.y);
        f4h(a2_1, ab.z, ab.w);
        g_ab[n1 * 16 + q] = ab;
        reinterpret_cast<float2*>(&g_bc[n1 * 16 + q])[0] =
            *reinterpret_cast<float2*>(&ab.z);
        reinterpret_cast<float4*>(g_res + n1 * CH)[q] = ar_1;
    }
}

// ================= CSR build (NBLK cascade; one edge per thread) ============
__global__ void hist_kernel(const int* __restrict__ dst) {
    int e = blockIdx.x * blockDim.x + threadIdx.x;
    if (e >= ETOT) return;
    int d = (e < NE) ? dst[e] : (e - NE);
    g_epos[e] = atomicAdd(&g_cnt[d], 1);
}

__global__ void scan1_kernel() {
    __shared__ int sm[256];
    int t = threadIdx.x;
    int i = blockIdx.x * 256 + t;
    sm[t] = (i < NN) ? g_cnt[i] : 0;
    __syncthreads();
    #pragma unroll
    for (int o = 128; o > 0; o >>= 1) {
        if (t < o) sm[t] += sm[t + o];
        __syncthreads();
    }
    if (t == 0) g_bsum[blockIdx.x] = sm[0];
}

__global__ void scan2_kernel() {
    __shared__ int sm[256];
    int t = threadIdx.x;
    int v = (t < NBLK) ? g_bsum[t] : 0;
    sm[t] = v;
    __syncthreads();
    #pragma unroll
    for (int o = 1; o < 256; o <<= 1) {
        int add = (t >= o) ? sm[t - o] : 0;
        __syncthreads();
        sm[t] += add;
        __syncthreads();
    }
    if (t < NBLK) g_bscan[t] = sm[t] - v;   // exclusive
}

// per-block exclusive scan + base; writes off and RE-ZEROES g_cnt so the
// next replay (and only then) sees a clean histogram — replaces init_cnt.
__global__ void scan3_kernel() {
    __shared__ int sm[256];
    int t = threadIdx.x;
    int i = blockIdx.x * 256 + t;
    int v = (i < NN) ? g_cnt[i] : 0;
    sm[t] = v;
    __syncthreads();
    #pragma unroll
    for (int o = 1; o < 256; o <<= 1) {
        int add = (t >= o) ? sm[t - o] : 0;
        __syncthreads();
        sm[t] += add;
        __syncthreads();
    }
    if (i < NN) {
        g_off[i] = g_bscan[blockIdx.x] + sm[t] - v;
        g_cnt[i] = 0;   // self-clean for the next call/replay
    }
    if (i == 0) g_off[NN] = ETOT;
}

// atomic-free scatter: position = segment offset + precomputed rank
__global__ void scatter_kernel(const int* __restrict__ src,
                               const int* __restrict__ dst) {
    int e = blockIdx.x * blockDim.x + threadIdx.x;
    if (e >= ETOT) return;
    int s, d;
    if (e < NE) { s = src[e]; d = dst[e]; }
    else        { s = e - NE; d = s; }
    g_ssrc[__ldg(&g_off[d]) + g_epos[e]] = s;
}

// ================= agg pass A: ftr[n] = sum(r[s]*el) / sum(el) ===============
// el = expsig(l_s + l_n). ONE LDG.128 per edge-lane ({l,r} packed halves).
__global__ void __launch_bounds__(256) aggA_kernel() {
    int n = blockIdx.x * 16 + (threadIdx.x >> 4);
    if (n >= NN) return;
    int q = threadIdx.x & 15;

    uint4 dab = __ldg(&g_ab[n * 16 + q]);
    float4 ldq = h4f(dab.x, dab.y);
    int i0 = __ldg(&g_off[n]);
    int i1 = __ldg(&g_off[n + 1]);

    float4 esum = make_float4(0.f, 0.f, 0.f, 0.f);
    float4 acc  = make_float4(0.f, 0.f, 0.f, 0.f);

    int i = i0;
    for (; i + 2 <= i1; i += 2) {
        int s0 = __ldg(&g_ssrc[i]);
        int s1 = __ldg(&g_ssrc[i + 1]);
        uint4 v0 = __ldg(&g_ab[s0 * 16 + q]);
        uint4 v1 = __ldg(&g_ab[s1 * 16 + q]);
        float4 ls0 = h4f(v0.x, v0.y);
        float4 rs0 = h4f(v0.z, v0.w);
        float4 ls1 = h4f(v1.x, v1.y);
        float4 rs1 = h4f(v1.z, v1.w);
        float4 e0 = make_float4(expsig(ls0.x+ldq.x), expsig(ls0.y+ldq.y),
                                expsig(ls0.z+ldq.z), expsig(ls0.w+ldq.w));
        float4 e1 = make_float4(expsig(ls1.x+ldq.x), expsig(ls1.y+ldq.y),
                                expsig(ls1.z+ldq.z), expsig(ls1.w+ldq.w));
        esum.x += e0.x + e1.x; esum.y += e0.y + e1.y;
        esum.z += e0.z + e1.z; esum.w += e0.w + e1.w;
        acc.x = fmaf(rs0.x, e0.x, acc.x); acc.x = fmaf(rs1.x, e1.x, acc.x);
        acc.y = fmaf(rs0.y, e0.y, acc.y); acc.y = fmaf(rs1.y, e1.y, acc.y);
        acc.z = fmaf(rs0.z, e0.z, acc.z); acc.z = fmaf(rs1.z, e1.z, acc.z);
        acc.w = fmaf(rs0.w, e0.w, acc.w); acc.w = fmaf(rs1.w, e1.w, acc.w);
    }
    if (i < i1) {
        int s0 = __ldg(&g_ssrc[i]);
        uint4 v0 = __ldg(&g_ab[s0 * 16 + q]);
        float4 ls0 = h4f(v0.x, v0.y);
        float4 rs0 = h4f(v0.z, v0.w);
        float4 e0 = make_float4(expsig(ls0.x+ldq.x), expsig(ls0.y+ldq.y),
                                expsig(ls0.z+ldq.z), expsig(ls0.w+ldq.w));
        esum.x += e0.x; esum.y += e0.y; esum.z += e0.z; esum.w += e0.w;
        acc.x = fmaf(rs0.x, e0.x, acc.x); acc.y = fmaf(rs0.y, e0.y, acc.y);
        acc.z = fmaf(rs0.z, e0.z, acc.z); acc.w = fmaf(rs0.w, e0.w, acc.w);
    }

    acc.x *= fast_rcp(esum.x); acc.y *= fast_rcp(esum.y);
    acc.z *= fast_rcp(esum.z); acc.w *= fast_rcp(esum.w);

    unsigned lo, hi;
    f4h(acc, lo, hi);
    float2 p;
    *reinterpret_cast<unsigned*>(&p.x) = lo;
    *reinterpret_cast<unsigned*>(&p.y) = hi;
    reinterpret_cast<float2*>(&g_bc[n * 16 + q])[1] = p;   // ftr halves
}

// ================= agg pass B: out = m0*(sum(ftr[s]*er)/sum(er)) + res =======
__global__ void __launch_bounds__(256) aggB_kernel(const float* __restrict__ m,
                                                   float* __restrict__ out) {
    int n = blockIdx.x * 16 + (threadIdx.x >> 4);
    if (n >= NN) return;
    int q = threadIdx.x & 15;

    uint4 dbc = __ldg(&g_bc[n * 16 + q]);
    float4 rdq = h4f(dbc.x, dbc.y);
    int i0 = __ldg(&g_off[n]);
    int i1 = __ldg(&g_off[n + 1]);

    float4 esum = make_float4(0.f, 0.f, 0.f, 0.f);
    float4 acc  = make_float4(0.f, 0.f, 0.f, 0.f);

    int i = i0;
    for (; i + 2 <= i1; i += 2) {
        int s0 = __ldg(&g_ssrc[i]);
        int s1 = __ldg(&g_ssrc[i + 1]);
        uint4 v0 = __ldg(&g_bc[s0 * 16 + q]);
        uint4 v1 = __ldg(&g_bc[s1 * 16 + q]);
        float4 rs0 = h4f(v0.x, v0.y);
        float4 f0  = h4f(v0.z, v0.w);
        float4 rs1 = h4f(v1.x, v1.y);
        float4 f1  = h4f(v1.z, v1.w);
        float4 e0 = make_float4(expsig(rs0.x+rdq.x), expsig(rs0.y+rdq.y),
                                expsig(rs0.z+rdq.z), expsig(rs0.w+rdq.w));
        float4 e1 = make_float4(expsig(rs1.x+rdq.x), expsig(rs1.y+rdq.y),
                                expsig(rs1.z+rdq.z), expsig(rs1.w+rdq.w));
        esum.x += e0.x + e1.x; esum.y += e0.y + e1.y;
        esum.z += e0.z + e1.z; esum.w += e0.w + e1.w;
        acc.x = fmaf(f0.x, e0.x, acc.x); acc.x = fmaf(f1.x, e1.x, acc.x);
        acc.y = fmaf(f0.y, e0.y, acc.y); acc.y = fmaf(f1.y, e1.y, acc.y);
        acc.z = fmaf(f0.z, e0.z, acc.z); acc.z = fmaf(f1.z, e1.z, acc.z);
        acc.w = fmaf(f0.w, e0.w, acc.w); acc.w = fmaf(f1.w, e1.w, acc.w);
    }
    if (i < i1) {
        int s0 = __ldg(&g_ssrc[i]);
        uint4 v0 = __ldg(&g_bc[s0 * 16 + q]);
        float4 rs0 = h4f(v0.x, v0.y);
        float4 f0  = h4f(v0.z, v0.w);
        float4 e0 = make_float4(expsig(rs0.x+rdq.x), expsig(rs0.y+rdq.y),
                                expsig(rs0.z+rdq.z), expsig(rs0.w+rdq.w));
        esum.x += e0.x; esum.y += e0.y; esum.z += e0.z; esum.w += e0.w;
        acc.x = fmaf(f0.x, e0.x, acc.x); acc.y = fmaf(f0.y, e0.y, acc.y);
        acc.z = fmaf(f0.z, e0.z, acc.z); acc.w = fmaf(f0.w, e0.w, acc.w);
    }

    float4 mv = __ldg(reinterpret_cast<const float4*>(m) + q);
    float4 rv = __ldg(reinterpret_cast<const float4*>(g_res + n * CH) + q);
    float4 o;
    o.x = fmaf(mv.x, acc.x * fast_rcp(esum.x), rv.x);
    o.y = fmaf(mv.y, acc.y * fast_rcp(esum.y), rv.y);
    o.z = fmaf(mv.z, acc.z * fast_rcp(esum.z), rv.z);
    o.w = fmaf(mv.w, acc.w * fast_rcp(esum.w), rv.w);
    reinterpret_cast<float4*>(out + n * CH)[q] = o;
}

extern "C" void kernel_launch(void* const* d_in, const int* in_sizes, int n_in,
                              void* d_out, int out_size) {
    const float* ndata = (const float*)d_in[0];
    const int*   src   = (const int*)d_in[1];
    const int*   dst   = (const int*)d_in[2];
    const float* W1    = (const float*)d_in[3];
    const float* b1    = (const float*)d_in[4];
    const float* W2    = (const float*)d_in[5];
    const float* b2    = (const float*)d_in[6];
    const float* Wres  = (const float*)d_in[7];
    const float* bres  = (const float*)d_in[8];
    const float* m     = (const float*)d_in[9];
    float* out = (float*)d_out;

    // side stream + fork/join events: created once on the first call
    // (the correctness call, which is NOT under graph capture).
    static cudaStream_t s2 = [] {
        cudaStream_t s;
        cudaStreamCreateWithFlags(&s, cudaStreamNonBlocking);
        return s;
    }();
    static cudaEvent_t evFork = [] {
        cudaEvent_t e;
        cudaEventCreateWithFlags(&e, cudaEventDisableTiming);
        return e;
    }();
    static cudaEvent_t evJoin = [] {
        cudaEvent_t e;
        cudaEventCreateWithFlags(&e, cudaEventDisableTiming);
        return e;
    }();

    // fork: s2 becomes a parallel branch of the capture DAG
    cudaEventRecord(evFork, 0);
    cudaStreamWaitEvent(s2, evFork, 0);

    // branch A (default stream): node projections
    node_proj_kernel<<<(NN + 31) / 32, 256>>>(ndata, W1, b1, W2, b2, Wres, bres);

    // branch B (s2): CSR build (g_cnt pre-zeroed by scan3 of the previous
    // call; zero-initialized at load for the first call)
    hist_kernel<<<(ETOT + 255) / 256, 256, 0, s2>>>(dst);
    scan1_kernel<<<NBLK, 256, 0, s2>>>();
    scan2_kernel<<<1, 256, 0, s2>>>();
    scan3_kernel<<<NBLK, 256, 0, s2>>>();
    scatter_kernel<<<(ETOT + 255) / 256, 256, 0, s2>>>(src, dst);

    // join: aggregation needs both branches
    cudaEventRecord(evJoin, s2);
    cudaStreamWaitEvent(0, evJoin, 0);

    aggA_kernel<<<(NN + 15) / 16, 256>>>();
    aggB_kernel<<<(NN + 15) / 16, 256>>>(m, out);
}